// round 11
// baseline (speedup 1.0000x reference)
#include <cuda_runtime.h>
#include <cstdint>

// GestureRNN: 2-layer ReLU RNN, B=4096, T=512, IN=10, H=32, NCLS=9.
// R10: R4's proven main recurrence (357us measured) + a rewritten xproj
// pre-pass: weights in REGISTERS (no smem FFMA operands), broadcast LDG
// of x rows, coalesced STG.32 of xp[b][t][j]. R4's pre-pass cost 195us
// from smem-operand FFMAs and 32-line scattered stores; this removes both.

typedef unsigned long long ull;

__device__ __forceinline__ ull ffma2(ull a, ull b, ull c) {
    ull d;
    asm("fma.rn.f32x2 %0, %1, %2, %3;" : "=l"(d) : "l"(a), "l"(b), "l"(c));
    return d;
}
__device__ __forceinline__ ull fadd2(ull a, ull b) {
    ull d;
    asm("add.rn.f32x2 %0, %1, %2;" : "=l"(d) : "l"(a), "l"(b));
    return d;
}
__device__ __forceinline__ float hsum2(ull a) {
    return __uint_as_float((unsigned)a) + __uint_as_float((unsigned)(a >> 32));
}

static constexpr int T_STEPS = 512;
static constexpr int BATCH   = 4096;
static constexpr int IN_DIM  = 10;
static constexpr int NCLS    = 9;
static constexpr int WARPS   = 4;   // main kernel: 128-thread CTAs

// Scratch: xp[b][t][j] = b_ih0[j] + b_hh0[j] + sum_i x[b][t][i]*Wih0[j][i]
__device__ float g_xp[(size_t)BATCH * T_STEPS * 32];

// ---------------- pre-pass: input projection, register weights ----------------
__global__ void __launch_bounds__(256) xproj_kernel(
    const float* __restrict__ x,
    const float* __restrict__ Wih0,
    const float* __restrict__ bih0, const float* __restrict__ bhh0)
{
    const int warp = threadIdx.x >> 5;
    const int lid  = threadIdx.x & 31;
    const int b    = blockIdx.x * 8 + warp;

    // lane lid owns output unit lid: Wih0 row in 5 packed f32x2 regs
    ull wx[5];
    {
        const ull* px = (const ull*)(Wih0 + lid * IN_DIM);  // 40B rows, 8B aligned
#pragma unroll
        for (int m = 0; m < 5; m++) wx[m] = px[m];
    }
    const float b0 = bih0[lid] + bhh0[lid];

    const float* xb = x + (size_t)b * (T_STEPS * IN_DIM);
    float* dst = g_xp + (size_t)b * T_STEPS * 32 + lid;

    // 1-step prefetch of the broadcast x row
    ull xr[5];
    {
        const ull* p = (const ull*)xb;
#pragma unroll
        for (int m = 0; m < 5; m++) xr[m] = p[m];
    }

#pragma unroll 4
    for (int t = 0; t < T_STEPS; t++) {
        ull a0 = ffma2(wx[0], xr[0], (ull)0);
        ull a1 = ffma2(wx[1], xr[1], (ull)0);
        a0 = ffma2(wx[2], xr[2], a0);
        a1 = ffma2(wx[3], xr[3], a1);
        a0 = ffma2(wx[4], xr[4], a0);
        const float val = b0 + hsum2(fadd2(a0, a1));

        // prefetch next row (clamped)
        const int tn = (t + 1 < T_STEPS) ? (t + 1) : t;
        const ull* q = (const ull*)(xb + tn * IN_DIM);
#pragma unroll
        for (int m = 0; m < 5; m++) xr[m] = q[m];

        dst[t * 32] = val;   // coalesced across lanes
    }
}

// ---------------- main recurrence (R4 verbatim: 357us measured) ----------------
struct __align__(16) WarpBuf {
    float h1[2][32];
    float h2[2][32];
};

__global__ void __launch_bounds__(WARPS * 32, 3) rnn_fused_kernel(
    const float* __restrict__ Whh0,
    const float* __restrict__ Wih1, const float* __restrict__ Whh1,
    const float* __restrict__ bih1, const float* __restrict__ bhh1,
    const float* __restrict__ Wfc,  const float* __restrict__ bfc,
    float* __restrict__ out)
{
    __shared__ WarpBuf buf[WARPS];

    const int w   = threadIdx.x >> 5;
    const int lid = threadIdx.x & 31;
    const int b   = blockIdx.x * WARPS + w;
    WarpBuf& wb = buf[w];

    // per-lane weight rows, packed f32x2 over k-pairs
    ull w0[16], wi1[16], wh1[16];
    {
        const ulonglong2* p0 = (const ulonglong2*)(Whh0 + lid * 32);
        const ulonglong2* p1 = (const ulonglong2*)(Wih1 + lid * 32);
        const ulonglong2* p2 = (const ulonglong2*)(Whh1 + lid * 32);
#pragma unroll
        for (int m = 0; m < 8; m++) {
            ulonglong2 a = p0[m]; w0[2*m]  = a.x; w0[2*m+1]  = a.y;
            ulonglong2 c = p1[m]; wi1[2*m] = c.x; wi1[2*m+1] = c.y;
            ulonglong2 d = p2[m]; wh1[2*m] = d.x; wh1[2*m+1] = d.y;
        }
    }
    const float b1 = bih1[lid] + bhh1[lid];

    wb.h2[0][lid] = 0.f;

    const float* xq = g_xp + (size_t)b * T_STEPS * 32 + lid;
    float rxp[4];
#pragma unroll
    for (int k = 0; k < 4; k++) rxp[k] = xq[k * 32];   // xp for t=0..3
    __syncwarp();

    ull carA = 0ull, carB = 0ull;   // carried w0 · h1_{t-1} partial

    for (int t4 = 0; t4 < T_STEPS; t4 += 4) {
#pragma unroll
        for (int k = 0; k < 4; k++) {
            const int t = t4 + k;
            const int p = k & 1;       // read parity  (== t & 1)
            const int q = p ^ 1;       // write parity

            // layer 0 finish: registers only
            float h1n = fmaxf(rxp[k] + hsum2(fadd2(carA, carB)), 0.f);

            // refill prefetch ring (xp for t+4)
            if (t + 4 < T_STEPS) rxp[k] = xq[(t + 4) * 32];

            wb.h1[p][lid] = h1n;
            __syncwarp();   // publishes h1_t and (prev step's) h2_{t-1}

            // fused block: h1_new -> wi1 (now) + w0 (carry); h2_old -> wh1
            const ulonglong2* h1p = (const ulonglong2*)wb.h1[p];
            const ulonglong2* h2p = (const ulonglong2*)wb.h2[p];
            ull aA = 0ull, aB = 0ull, cA = 0ull, cB = 0ull;
            ull nA = 0ull, nB = 0ull;
#pragma unroll
            for (int m = 0; m < 8; m++) {
                ulonglong2 qa = h1p[m];
                ulonglong2 ra = h2p[m];
                aA = ffma2(wi1[2*m],   qa.x, aA);
                aB = ffma2(wi1[2*m+1], qa.y, aB);
                nA = ffma2(w0[2*m],    qa.x, nA);
                nB = ffma2(w0[2*m+1],  qa.y, nB);
                cA = ffma2(wh1[2*m],   ra.x, cA);
                cB = ffma2(wh1[2*m+1], ra.y, cB);
            }
            float h2n = fmaxf(b1 + hsum2(fadd2(fadd2(aA, aB), fadd2(cA, cB))), 0.f);
            wb.h2[q][lid] = h2n;   // published by NEXT step's syncwarp
            carA = nA; carB = nB;
        }
    }
    __syncwarp();

    // classifier head: t=511 wrote h2 buffer 0
    if (lid < NCLS) {
        float o = bfc[lid];
        const float* wr  = Wfc + lid * 32;
        const float* h2f = wb.h2[0];
#pragma unroll
        for (int j = 0; j < 32; j++) o += h2f[j] * wr[j];
        out[(size_t)b * NCLS + lid] = o;
    }
}

extern "C" void kernel_launch(void* const* d_in, const int* in_sizes, int n_in,
                              void* d_out, int out_size)
{
    const float* x    = (const float*)d_in[0];
    const float* Wih0 = (const float*)d_in[1];
    const float* Whh0 = (const float*)d_in[2];
    const float* bih0 = (const float*)d_in[3];
    const float* bhh0 = (const float*)d_in[4];
    const float* Wih1 = (const float*)d_in[5];
    const float* Whh1 = (const float*)d_in[6];
    const float* bih1 = (const float*)d_in[7];
    const float* bhh1 = (const float*)d_in[8];
    const float* Wfc  = (const float*)d_in[9];
    const float* bfc  = (const float*)d_in[10];
    float* out = (float*)d_out;

    xproj_kernel<<<BATCH / 8, 256>>>(x, Wih0, bih0, bhh0);
    rnn_fused_kernel<<<BATCH / WARPS, WARPS * 32>>>(
        Whh0, Wih1, Whh1, bih1, bhh1, Wfc, bfc, out);
}

// round 12
// speedup vs baseline: 1.2722x; 1.2722x over previous
#include <cuda_runtime.h>
#include <cstdint>

// GestureRNN: 2-layer ReLU RNN, B=4096, T=512, IN=10, H=32, NCLS=9.
// R12: R4's main recurrence (357us measured, FMA-bound) with the input
// projection fused IN at near-zero cost:
//  - x rows are 40B -> each 2-step group is an aligned 80B = 5x LDG.128,
//    read as ulonglong2 so each 16B gives two packed f32x2 operands
//    directly (NO pack movs - R7's mistake).
//  - the 5 seed ffma2 (xw . x_{t+1}) REPLACE the zero-init of the carry
//    chains nA/nB, so layer-0's xp costs 5 ffma2 per step, nothing else.
//  - A/B double-buffered x-group registers, 2-group prefetch distance,
//    clamped tail load (the t=511 seed feeds a dead carry only).

typedef unsigned long long ull;

__device__ __forceinline__ ull ffma2(ull a, ull b, ull c) {
    ull d;
    asm("fma.rn.f32x2 %0, %1, %2, %3;" : "=l"(d) : "l"(a), "l"(b), "l"(c));
    return d;
}
__device__ __forceinline__ ull fadd2(ull a, ull b) {
    ull d;
    asm("add.rn.f32x2 %0, %1, %2;" : "=l"(d) : "l"(a), "l"(b));
    return d;
}
__device__ __forceinline__ float hsum2(ull a) {
    return __uint_as_float((unsigned)a) + __uint_as_float((unsigned)(a >> 32));
}

static constexpr int T_STEPS = 512;
static constexpr int BATCH   = 4096;
static constexpr int IN_DIM  = 10;
static constexpr int NCLS    = 9;
static constexpr int WARPS   = 4;   // 128-thread CTAs

struct __align__(16) WarpBuf {
    float h1[2][32];
    float h2[2][32];
};

__global__ void __launch_bounds__(WARPS * 32, 3) rnn_fused_kernel(
    const float* __restrict__ x,
    const float* __restrict__ Wih0, const float* __restrict__ Whh0,
    const float* __restrict__ bih0, const float* __restrict__ bhh0,
    const float* __restrict__ Wih1, const float* __restrict__ Whh1,
    const float* __restrict__ bih1, const float* __restrict__ bhh1,
    const float* __restrict__ Wfc,  const float* __restrict__ bfc,
    float* __restrict__ out)
{
    __shared__ WarpBuf buf[WARPS];

    const int w   = threadIdx.x >> 5;
    const int lid = threadIdx.x & 31;
    const int b   = blockIdx.x * WARPS + w;
    WarpBuf& wb = buf[w];

    // ---- per-lane weight rows, packed f32x2 over k-pairs ----
    ull w0[16], wi1[16], wh1[16], xw[5];
    {
        const ulonglong2* p0 = (const ulonglong2*)(Whh0 + lid * 32);
        const ulonglong2* p1 = (const ulonglong2*)(Wih1 + lid * 32);
        const ulonglong2* p2 = (const ulonglong2*)(Whh1 + lid * 32);
#pragma unroll
        for (int m = 0; m < 8; m++) {
            ulonglong2 a = p0[m]; w0[2*m]  = a.x; w0[2*m+1]  = a.y;
            ulonglong2 c = p1[m]; wi1[2*m] = c.x; wi1[2*m+1] = c.y;
            ulonglong2 d = p2[m]; wh1[2*m] = d.x; wh1[2*m+1] = d.y;
        }
        const ull* px = (const ull*)(Wih0 + lid * IN_DIM);  // 40B rows, 8B aligned
#pragma unroll
        for (int m = 0; m < 5; m++) xw[m] = px[m];
    }
    const float b0f = bih0[lid] + bhh0[lid];
    const float b1f = bih1[lid] + bhh1[lid];

    wb.h2[0][lid] = 0.f;

    // x groups: group g = steps 2g,2g+1 = 80B = 5 x ulonglong2 (16B aligned:
    // batch base is 20480B, group stride 80B).
    const ulonglong2* xgp = (const ulonglong2*)(x + (size_t)b * (T_STEPS * IN_DIM));

    ulonglong2 xA[5], xB[5];
#pragma unroll
    for (int j = 0; j < 5; j++) { xA[j] = xgp[j]; xB[j] = xgp[5 + j]; }

    // carry seed for step 0: xw . x_0 (even pairs of group 0)
    ull carA, carB;
    carA = ffma2(xw[0], xA[0].x, (ull)0);
    carB = ffma2(xw[1], xA[0].y, (ull)0);
    carA = ffma2(xw[2], xA[1].x, carA);
    carB = ffma2(xw[3], xA[1].y, carB);
    carA = ffma2(xw[4], xA[2].x, carA);

    // One recurrence step. P = parity (t&1), seeds s0..s4 = packed pairs of
    // x_{t+1} feeding the carry-chain init.
#define RNN_STEP(P, s0, s1, s2, s3, s4)                                       \
    {                                                                         \
        const int Q = (P) ^ 1;                                                \
        float h1n = fmaxf(b0f + hsum2(fadd2(carA, carB)), 0.f);               \
        wb.h1[(P)][lid] = h1n;                                                \
        __syncwarp();                                                         \
        const ulonglong2* h1p = (const ulonglong2*)wb.h1[(P)];                \
        const ulonglong2* h2p = (const ulonglong2*)wb.h2[(P)];                \
        ull aA = 0ull, aB = 0ull, cA = 0ull, cB = 0ull;                       \
        ull nA = ffma2(xw[0], (s0), (ull)0);                                  \
        ull nB = ffma2(xw[1], (s1), (ull)0);                                  \
        nA = ffma2(xw[2], (s2), nA);                                          \
        nB = ffma2(xw[3], (s3), nB);                                          \
        nA = ffma2(xw[4], (s4), nA);                                          \
        _Pragma("unroll")                                                     \
        for (int m = 0; m < 8; m++) {                                         \
            ulonglong2 qa = h1p[m];                                           \
            ulonglong2 ra = h2p[m];                                           \
            aA = ffma2(wi1[2*m],   qa.x, aA);                                 \
            aB = ffma2(wi1[2*m+1], qa.y, aB);                                 \
            nA = ffma2(w0[2*m],    qa.x, nA);                                 \
            nB = ffma2(w0[2*m+1],  qa.y, nB);                                 \
            cA = ffma2(wh1[2*m],   ra.x, cA);                                 \
            cB = ffma2(wh1[2*m+1], ra.y, cB);                                 \
        }                                                                     \
        float h2n = fmaxf(b1f + hsum2(fadd2(fadd2(aA, aB), fadd2(cA, cB))), 0.f); \
        wb.h2[Q][lid] = h2n;                                                  \
        carA = nA; carB = nB;                                                 \
    }

    for (int t4 = 0; t4 < T_STEPS; t4 += 4) {
        const int g = t4 >> 1;           // xA = G(g), xB = G(g+1)

        // step t4 (P=0): seed x_{t4+1} = odd of G(g)
        RNN_STEP(0, xA[2].y, xA[3].x, xA[3].y, xA[4].x, xA[4].y);

        // reload xA <- G(g+2) (clamped; garbage only seeds the dead final carry)
        {
            const int gn = (g + 2 < T_STEPS / 2) ? (g + 2) : (T_STEPS / 2 - 1);
            const ulonglong2* src = xgp + 5 * gn;
#pragma unroll
            for (int j = 0; j < 5; j++) xA[j] = src[j];
        }

        // step t4+1 (P=1): seed x_{t4+2} = even of G(g+1)
        RNN_STEP(1, xB[0].x, xB[0].y, xB[1].x, xB[1].y, xB[2].x);

        // step t4+2 (P=0): seed x_{t4+3} = odd of G(g+1)
        RNN_STEP(0, xB[2].y, xB[3].x, xB[3].y, xB[4].x, xB[4].y);

        // reload xB <- G(g+3) (clamped)
        {
            const int gn = (g + 3 < T_STEPS / 2) ? (g + 3) : (T_STEPS / 2 - 1);
            const ulonglong2* src = xgp + 5 * gn;
#pragma unroll
            for (int j = 0; j < 5; j++) xB[j] = src[j];
        }

        // step t4+3 (P=1): seed x_{t4+4} = even of G(g+2) (reloaded xA)
        RNN_STEP(1, xA[0].x, xA[0].y, xA[1].x, xA[1].y, xA[2].x);
    }
#undef RNN_STEP
    __syncwarp();

    // classifier head: t=511 (P=1) wrote h2 parity 0
    if (lid < NCLS) {
        float o = bfc[lid];
        const float* wr  = Wfc + lid * 32;
        const float* h2f = wb.h2[0];
#pragma unroll
        for (int j = 0; j < 32; j++) o += h2f[j] * wr[j];
        out[(size_t)b * NCLS + lid] = o;
    }
}

extern "C" void kernel_launch(void* const* d_in, const int* in_sizes, int n_in,
                              void* d_out, int out_size)
{
    const float* x    = (const float*)d_in[0];
    const float* Wih0 = (const float*)d_in[1];
    const float* Whh0 = (const float*)d_in[2];
    const float* bih0 = (const float*)d_in[3];
    const float* bhh0 = (const float*)d_in[4];
    const float* Wih1 = (const float*)d_in[5];
    const float* Whh1 = (const float*)d_in[6];
    const float* bih1 = (const float*)d_in[7];
    const float* bhh1 = (const float*)d_in[8];
    const float* Wfc  = (const float*)d_in[9];
    const float* bfc  = (const float*)d_in[10];
    float* out = (float*)d_out;

    rnn_fused_kernel<<<BATCH / WARPS, WARPS * 32>>>(
        x, Wih0, Whh0, bih0, bhh0, Wih1, Whh1, bih1, bhh1, Wfc, bfc, out);
}